// round 14
// baseline (speedup 1.0000x reference)
#include <cuda_runtime.h>

// Problem constants
#define LL 8
#define KK 8
#define NN 1048576
#define NVEC (NN / 4)          // 262144 float4 per (l,k) row
#define NPAIR 36               // triangular 8x8
#define NSM 148
#define OCC 2
#define NCTA (NSM * OCC)       // 296 CTAs, all resident (2/SM guaranteed)
#define THREADS 256
#define PAD 32                 // pad tri entries to separate 128B lines

// Balanced partition: NVEC = 296*885 + 184
#define BASE_LEN 885
#define REM 184

// Scratch (allocation-free rule: __device__ globals).
// Zero-initialized at module load; reset in-pipeline for graph replays.
__device__ float    g_tri[LL][NPAIR * PAD];   // padded triangular Gram sums
__device__ unsigned g_bar[LL + 1];             // per-layer counters + done ctr

__device__ __forceinline__ int tri_idx(int a, int b) {
    return a * KK - (a * (a - 1)) / 2 + (b - a);
}

// L2 evict_last policy: lines loaded with this hint are sticky in L2.
__device__ __forceinline__ unsigned long long mk_sticky_policy() {
    unsigned long long p;
    asm("createpolicy.fractional.L2::evict_last.b64 %0, 1.0;" : "=l"(p));
    return p;
}
__device__ __forceinline__ float4 ld_sticky(const float4* a,
                                            unsigned long long pol) {
    float4 v;
    asm volatile("ld.global.L2::cache_hint.v4.f32 {%0,%1,%2,%3}, [%4], %5;"
                 : "=f"(v.x), "=f"(v.y), "=f"(v.z), "=f"(v.w)
                 : "l"(a), "l"(pol));
    return v;
}

// ---------------------------------------------------------------------------
// Persistent fused kernel, barrier-hiding schedule + L2 policy control +
// EXACT per-CTA load balance (contiguous regions of 885/886 float4; the old
// grid-stride gave CTAs 0-135 4 iterations vs 3 for the rest => 29% skew
// that exposed every barrier wait).
//   gram(0); arrive(0)
//   for l: { gram(l+1) [evict_last]; arrive(l+1); wait(l);
//            reset(l-2) [CTA0, free]; softmax(l); apply(l) [demote] }
// ---------------------------------------------------------------------------
__global__ void __launch_bounds__(THREADS, OCC)
fused_kernel(const float* __restrict__ last,
             const float* __restrict__ deltas,
             const float* __restrict__ beta,
             float* __restrict__ out) {
    const int tid  = threadIdx.x;
    const int cta  = blockIdx.x;
    const int lane = tid & 31;
    const int wid  = tid >> 5;
    const unsigned long long pol = mk_sticky_policy();

    // balanced contiguous region for this CTA
    const int start = cta * BASE_LEN + (cta < REM ? cta : REM);
    const int len   = BASE_LEN + (cta < REM ? 1 : 0);      // 885 or 886

    __shared__ float sred[8][NPAIR];
    __shared__ float Ws[KK * KK];

    // ------------------- gram phase for one layer -------------------------
    auto do_gram = [&](int l) {
        const float4* __restrict__ d4 =
            reinterpret_cast<const float4*>(deltas) + (size_t)l * KK * NVEC;

        float acc[NPAIR];
#pragma unroll
        for (int p = 0; p < NPAIR; ++p) acc[p] = 0.0f;

        // region covered in chunk-pairs of 512 (16 loads in flight)
#pragma unroll
        for (int o = 0; o < 1024; o += 512) {
            const int iA = o + tid;
            const int iB = o + 256 + tid;
            const bool aA = iA < len;
            const bool aB = iB < len;
            const size_t gA = (size_t)(start + iA);
            const size_t gB = (size_t)(start + iB);
            float4 v0[KK], v1[KK];
#pragma unroll
            for (int j = 0; j < KK; ++j)
                v0[j] = aA ? ld_sticky(&d4[(size_t)j * NVEC + gA], pol)
                           : make_float4(0.f, 0.f, 0.f, 0.f);
#pragma unroll
            for (int j = 0; j < KK; ++j)
                v1[j] = aB ? ld_sticky(&d4[(size_t)j * NVEC + gB], pol)
                           : make_float4(0.f, 0.f, 0.f, 0.f);
            int p = 0;
#pragma unroll
            for (int a = 0; a < KK; ++a) {
#pragma unroll
                for (int b = a; b < KK; ++b) {
                    float s = fmaf(v0[a].x, v0[b].x, acc[p]);
                    s = fmaf(v0[a].y, v0[b].y, s);
                    s = fmaf(v0[a].z, v0[b].z, s);
                    s = fmaf(v0[a].w, v0[b].w, s);
                    s = fmaf(v1[a].x, v1[b].x, s);
                    s = fmaf(v1[a].y, v1[b].y, s);
                    s = fmaf(v1[a].z, v1[b].z, s);
                    s = fmaf(v1[a].w, v1[b].w, s);
                    acc[p] = s;
                    ++p;
                }
            }
        }

        // cross-warp reduce (sred reuse guarded by this syncthreads)
        __syncthreads();
#pragma unroll
        for (int p = 0; p < NPAIR; ++p) {
            float v = acc[p];
#pragma unroll
            for (int o = 16; o > 0; o >>= 1)
                v += __shfl_down_sync(0xffffffffu, v, o);
            if (lane == 0) sred[wid][p] = v;
        }
        __syncthreads();
        if (tid < NPAIR) {
            float s = 0.0f;
#pragma unroll
            for (int w = 0; w < 8; ++w) s += sred[w][tid];
            atomicAdd(&g_tri[l][tid * PAD], s);
        }
        // arrive: release our g_tri contribution, bump layer counter
        __threadfence();
        __syncthreads();
        if (tid == 0) atomicAdd(&g_bar[l], 1u);
    };

    // ------------------------------- schedule -----------------------------
    do_gram(0);

    for (int l = 0; l < LL; ++l) {
        if (l + 1 < LL) do_gram(l + 1);   // hides the wait below

        // wait for all gram(l) contributions
        if (tid == 0) {
            while (*(volatile unsigned*)&g_bar[l] < NCTA) __nanosleep(32);
        }
        __syncthreads();
        __threadfence();

        // free in-pipeline reset: all CTAs passed arrive(l), which follows
        // their softmax(l-2) in program order => g_tri[l-2] has no readers.
        if (cta == 0 && l >= 2) {
            if (tid < NPAIR) g_tri[l - 2][tid * PAD] = 0.0f;
            if (tid == 0) *(volatile unsigned*)&g_bar[l - 2] = 0u;
        }

        // softmax -> Ws in smem (every CTA redundantly; 8 threads)
        if (tid < KK) {
            const int k = tid;
            const float scale = rsqrtf((float)NN);
            float v[KK];
            float m = -1e30f;
#pragma unroll
            for (int j = 0; j < KK; ++j) {
                int a = k < j ? k : j;
                int b = k < j ? j : k;
                v[j] = g_tri[l][tri_idx(a, b) * PAD] * scale;
                m = fmaxf(m, v[j]);
            }
            float s = 0.0f;
#pragma unroll
            for (int j = 0; j < KK; ++j) {
                v[j] = __expf(v[j] - m);
                s += v[j];
            }
            float inv = 1.0f / s;
            float bcl = fminf(fmaxf(beta[l * KK + k], 0.0f), 1.0f);
#pragma unroll
            for (int j = 0; j < KK; ++j)
                Ws[k * KK + j] = bcl * v[j] * inv + ((j == k) ? 1.0f : 0.0f);
        }
        __syncthreads();

        // apply: out = last + Ws * deltas over the same balanced region.
        // Last reader of deltas(l): __ldcs demotes consumed lines.
        const float4* __restrict__ d4 =
            reinterpret_cast<const float4*>(deltas) + (size_t)l * KK * NVEC;
        const float4* __restrict__ p4 =
            reinterpret_cast<const float4*>(last) + (size_t)l * KK * NVEC;
        float4* __restrict__ o4 =
            reinterpret_cast<float4*>(out) + (size_t)l * KK * NVEC;

#pragma unroll
        for (int o = 0; o < 1024; o += 256) {
            const int idx = o + tid;
            if (idx < len) {
                const size_t gi = (size_t)(start + idx);
                float4 oacc[KK];
#pragma unroll
                for (int k = 0; k < KK; ++k)
                    oacc[k] = __ldcs(&p4[(size_t)k * NVEC + gi]);   // stream
#pragma unroll
                for (int j = 0; j < KK; ++j) {
                    float4 v = __ldcs(&d4[(size_t)j * NVEC + gi]);  // L2 + demote
#pragma unroll
                    for (int k = 0; k < KK; ++k) {
                        float w = Ws[k * KK + j];
                        oacc[k].x = fmaf(w, v.x, oacc[k].x);
                        oacc[k].y = fmaf(w, v.y, oacc[k].y);
                        oacc[k].z = fmaf(w, v.z, oacc[k].z);
                        oacc[k].w = fmaf(w, v.w, oacc[k].w);
                    }
                }
#pragma unroll
                for (int k = 0; k < KK; ++k)
                    __stcs(&o4[(size_t)k * NVEC + gi], oacc[k]);    // stream
            }
        }
        __syncthreads();   // Ws/sred safe for next layer's reuse
    }

    // ---- tail: reset remaining scratch (layers 6,7 + counters) -----------
    __threadfence();                     // order prior atomics before arrive
    if (tid == 0) atomicAdd(&g_bar[LL], 1u);
    if (cta == 0) {
        if (tid == 0) {
            while (*(volatile unsigned*)&g_bar[LL] < NCTA) __nanosleep(32);
        }
        __syncthreads();                 // all of CTA0 sees "everyone done"
        if (tid < NPAIR) {
            g_tri[LL - 2][tid * PAD] = 0.0f;
            g_tri[LL - 1][tid * PAD] = 0.0f;
        }
        if (tid == 0) {
            g_bar[LL - 2] = 0u;
            g_bar[LL - 1] = 0u;
            g_bar[LL]     = 0u;
        }
        __threadfence();
    }
}

// ---------------------------------------------------------------------------
extern "C" void kernel_launch(void* const* d_in, const int* in_sizes, int n_in,
                              void* d_out, int out_size) {
    const float* last_params = (const float*)d_in[0];
    const float* deltas      = (const float*)d_in[1];
    const float* beta        = (const float*)d_in[2];
    float* out               = (float*)d_out;

    fused_kernel<<<NCTA, THREADS>>>(last_params, deltas, beta, out);
}

// round 15
// speedup vs baseline: 1.0271x; 1.0271x over previous
#include <cuda_runtime.h>

// Problem constants
#define LL 8
#define KK 8
#define NN 1048576
#define NVEC (NN / 4)          // 262144 float4 per (l,k) row
#define NPAIR 36               // triangular 8x8
#define NSM 148
#define OCC 2
#define NCTA (NSM * OCC)       // 296 CTAs, all resident (2/SM guaranteed)
#define THREADS 256
#define PAD 32                 // pad tri entries to separate 128B lines

// Grid-stride geometry: S = NCTA*THREADS = 75776.
// 3 full strides cover 227328; remainder 34816 = 296*117 + 184 is spread
// evenly across CTAs (117 or 118 each) instead of landing on CTAs 0-135.
#define GS (NCTA * THREADS)            // 75776
#define FULL3 (3 * GS)                 // 227328
#define REM_BASE 117
#define REM_EXTRA 184                  // first 184 CTAs get 118

// Scratch (allocation-free rule: __device__ globals)
__device__ float    g_tri[LL][NPAIR * PAD];   // padded triangular Gram sums
__device__ unsigned g_bar[LL];                 // per-layer barrier counters

__device__ __forceinline__ int tri_idx(int a, int b) {
    return a * KK - (a * (a - 1)) / 2 + (b - a);
}

// L2 evict_last policy: lines loaded with this hint are sticky in L2.
__device__ __forceinline__ unsigned long long mk_sticky_policy() {
    unsigned long long p;
    asm("createpolicy.fractional.L2::evict_last.b64 %0, 1.0;" : "=l"(p));
    return p;
}
__device__ __forceinline__ float4 ld_sticky(const float4* a,
                                            unsigned long long pol) {
    float4 v;
    asm volatile("ld.global.L2::cache_hint.v4.f32 {%0,%1,%2,%3}, [%4], %5;"
                 : "=f"(v.x), "=f"(v.y), "=f"(v.z), "=f"(v.w)
                 : "l"(a), "l"(pol));
    return v;
}

// ---------------------------------------------------------------------------
// Init: reset barrier counters + zero tri accumulators (every replay)
// ---------------------------------------------------------------------------
__global__ void init_kernel() {
    const int t = threadIdx.x;
    if (t < LL) g_bar[t] = 0u;
    float* p = reinterpret_cast<float*>(g_tri);
    for (int i = t; i < LL * NPAIR * PAD; i += blockDim.x) p[i] = 0.0f;
}

// ---------------------------------------------------------------------------
// Persistent fused kernel = R12 (best) + balanced remainder:
//   gram(0); arrive(0)
//   for l: { gram(l+1) [evict_last]; arrive(l+1); wait(l); softmax(l);
//            apply(l) [deltas demoted on last read] }
// Each CTA: 3 full grid-stride iterations (identical pattern to R12) plus
// an even 117/118-element slice of the remainder -> per-CTA work equalized.
// ---------------------------------------------------------------------------
__global__ void __launch_bounds__(THREADS, OCC)
fused_kernel(const float* __restrict__ last,
             const float* __restrict__ deltas,
             const float* __restrict__ beta,
             float* __restrict__ out) {
    const int tid  = threadIdx.x;
    const int cta  = blockIdx.x;
    const int lane = tid & 31;
    const int wid  = tid >> 5;
    const unsigned long long pol = mk_sticky_policy();

    const int base = cta * THREADS + tid;
    // balanced remainder slice for this CTA
    const int rlen   = REM_BASE + (cta < REM_EXTRA ? 1 : 0);        // 117/118
    const int rstart = FULL3 + cta * REM_BASE + (cta < REM_EXTRA ? cta : REM_EXTRA);
    const int ridx   = rstart + tid;            // valid iff tid < rlen
    const bool rok   = tid < rlen;

    __shared__ float sred[8][NPAIR];
    __shared__ float Ws[KK * KK];

    // ------------------- gram phase for one layer -------------------------
    auto do_gram = [&](int l) {
        const float4* __restrict__ d4 =
            reinterpret_cast<const float4*>(deltas) + (size_t)l * KK * NVEC;

        float acc[NPAIR];
#pragma unroll
        for (int p = 0; p < NPAIR; ++p) acc[p] = 0.0f;

        // pair 1: strides 0 and 1 (always valid); pair 2: stride 2 + remainder
#pragma unroll
        for (int pair = 0; pair < 2; ++pair) {
            const int iA = base + (2 * pair) * GS;                 // valid
            const int iB = (pair == 0) ? base + GS : ridx;         // pair1: valid
            const bool okB = (pair == 0) ? true : rok;
            float4 v0[KK], v1[KK];
#pragma unroll
            for (int j = 0; j < KK; ++j)
                v0[j] = ld_sticky(&d4[(size_t)j * NVEC + iA], pol);
#pragma unroll
            for (int j = 0; j < KK; ++j)
                v1[j] = okB ? ld_sticky(&d4[(size_t)j * NVEC + iB], pol)
                            : make_float4(0.f, 0.f, 0.f, 0.f);
            int p = 0;
#pragma unroll
            for (int a = 0; a < KK; ++a) {
#pragma unroll
                for (int b = a; b < KK; ++b) {
                    float s = fmaf(v0[a].x, v0[b].x, acc[p]);
                    s = fmaf(v0[a].y, v0[b].y, s);
                    s = fmaf(v0[a].z, v0[b].z, s);
                    s = fmaf(v0[a].w, v0[b].w, s);
                    s = fmaf(v1[a].x, v1[b].x, s);
                    s = fmaf(v1[a].y, v1[b].y, s);
                    s = fmaf(v1[a].z, v1[b].z, s);
                    s = fmaf(v1[a].w, v1[b].w, s);
                    acc[p] = s;
                    ++p;
                }
            }
        }

        // cross-warp reduce (sred reuse guarded by this syncthreads)
        __syncthreads();
#pragma unroll
        for (int p = 0; p < NPAIR; ++p) {
            float v = acc[p];
#pragma unroll
            for (int o = 16; o > 0; o >>= 1)
                v += __shfl_down_sync(0xffffffffu, v, o);
            if (lane == 0) sred[wid][p] = v;
        }
        __syncthreads();
        if (tid < NPAIR) {
            float s = 0.0f;
#pragma unroll
            for (int w = 0; w < 8; ++w) s += sred[w][tid];
            atomicAdd(&g_tri[l][tid * PAD], s);
        }
        // arrive: release our g_tri contribution, bump layer counter
        __threadfence();
        __syncthreads();
        if (tid == 0) atomicAdd(&g_bar[l], 1u);
    };

    // ------------------------------- schedule -----------------------------
    do_gram(0);

    for (int l = 0; l < LL; ++l) {
        if (l + 1 < LL) do_gram(l + 1);   // hides the wait below

        // wait for all gram(l) contributions
        if (tid == 0) {
            while (*(volatile unsigned*)&g_bar[l] < NCTA) __nanosleep(32);
        }
        __syncthreads();
        __threadfence();

        // softmax -> Ws in smem (every CTA redundantly; 8 threads)
        if (tid < KK) {
            const int k = tid;
            const float scale = rsqrtf((float)NN);
            float v[KK];
            float m = -1e30f;
#pragma unroll
            for (int j = 0; j < KK; ++j) {
                int a = k < j ? k : j;
                int b = k < j ? j : k;
                v[j] = g_tri[l][tri_idx(a, b) * PAD] * scale;
                m = fmaxf(m, v[j]);
            }
            float s = 0.0f;
#pragma unroll
            for (int j = 0; j < KK; ++j) {
                v[j] = __expf(v[j] - m);
                s += v[j];
            }
            float inv = 1.0f / s;
            float bcl = fminf(fmaxf(beta[l * KK + k], 0.0f), 1.0f);
#pragma unroll
            for (int j = 0; j < KK; ++j)
                Ws[k * KK + j] = bcl * v[j] * inv + ((j == k) ? 1.0f : 0.0f);
        }
        __syncthreads();

        // apply: out = last + Ws * deltas. 3 full strides + remainder slice.
        // Last reader of deltas(l): __ldcs demotes consumed lines.
        const float4* __restrict__ d4 =
            reinterpret_cast<const float4*>(deltas) + (size_t)l * KK * NVEC;
        const float4* __restrict__ p4 =
            reinterpret_cast<const float4*>(last) + (size_t)l * KK * NVEC;
        float4* __restrict__ o4 =
            reinterpret_cast<float4*>(out) + (size_t)l * KK * NVEC;

#pragma unroll
        for (int it = 0; it < 4; ++it) {
            const int i = (it < 3) ? base + it * GS : ridx;
            const bool ok = (it < 3) ? true : rok;
            if (ok) {
                float4 oacc[KK];
#pragma unroll
                for (int k = 0; k < KK; ++k)
                    oacc[k] = __ldcs(&p4[(size_t)k * NVEC + i]);   // stream
#pragma unroll
                for (int j = 0; j < KK; ++j) {
                    float4 v = __ldcs(&d4[(size_t)j * NVEC + i]);  // L2 + demote
#pragma unroll
                    for (int k = 0; k < KK; ++k) {
                        float w = Ws[k * KK + j];
                        oacc[k].x = fmaf(w, v.x, oacc[k].x);
                        oacc[k].y = fmaf(w, v.y, oacc[k].y);
                        oacc[k].z = fmaf(w, v.z, oacc[k].z);
                        oacc[k].w = fmaf(w, v.w, oacc[k].w);
                    }
                }
#pragma unroll
                for (int k = 0; k < KK; ++k)
                    __stcs(&o4[(size_t)k * NVEC + i], oacc[k]);    // stream
            }
        }
        __syncthreads();   // Ws/sred safe for next layer's reuse
    }
}

// ---------------------------------------------------------------------------
extern "C" void kernel_launch(void* const* d_in, const int* in_sizes, int n_in,
                              void* d_out, int out_size) {
    const float* last_params = (const float*)d_in[0];
    const float* deltas      = (const float*)d_in[1];
    const float* beta        = (const float*)d_in[2];
    float* out               = (float*)d_out;

    init_kernel<<<1, 1024>>>();
    fused_kernel<<<NCTA, THREADS>>>(last_params, deltas, beta, out);
}

// round 16
// speedup vs baseline: 1.1233x; 1.0937x over previous
#include <cuda_runtime.h>

// Problem constants
#define LL 8
#define KK 8
#define NN 1048576
#define NVEC (NN / 4)          // 262144 float4 per (l,k) row
#define NPAIR 36               // triangular 8x8
#define NSM 148
#define OCC 1
#define NCTA 148               // one 512-thread CTA per SM, all resident
#define THREADS 512
#define NWARP (THREADS / 32)   // 16
#define PAD 32                 // pad tri entries to separate 128B lines
#define GS (NCTA * THREADS)    // 75776 — identical stride to the R12 best

// Scratch (allocation-free rule: __device__ globals)
__device__ float    g_tri[LL][NPAIR * PAD];   // padded triangular Gram sums
__device__ unsigned g_bar[LL];                 // per-layer barrier counters

__device__ __forceinline__ int tri_idx(int a, int b) {
    return a * KK - (a * (a - 1)) / 2 + (b - a);
}

// L2 evict_last policy: lines loaded with this hint are sticky in L2.
__device__ __forceinline__ unsigned long long mk_sticky_policy() {
    unsigned long long p;
    asm("createpolicy.fractional.L2::evict_last.b64 %0, 1.0;" : "=l"(p));
    return p;
}
__device__ __forceinline__ float4 ld_sticky(const float4* a,
                                            unsigned long long pol) {
    float4 v;
    asm volatile("ld.global.L2::cache_hint.v4.f32 {%0,%1,%2,%3}, [%4], %5;"
                 : "=f"(v.x), "=f"(v.y), "=f"(v.z), "=f"(v.w)
                 : "l"(a), "l"(pol));
    return v;
}

// ---------------------------------------------------------------------------
// Init: reset barrier counters + zero tri accumulators (every replay)
// ---------------------------------------------------------------------------
__global__ void init_kernel() {
    const int t = threadIdx.x;
    if (t < LL) g_bar[t] = 0u;
    float* p = reinterpret_cast<float*>(g_tri);
    for (int i = t; i < LL * NPAIR * PAD; i += blockDim.x) p[i] = 0.0f;
}

// ---------------------------------------------------------------------------
// Persistent fused kernel == R12 best (identical memory pattern), with CTA
// pairs merged: 148 x 512 threads. Global thread->index map is bit-identical
// to R12; only synchronization granularity changes (148 arrivals/polls per
// layer instead of 296).
//   gram(0); arrive(0)
//   for l: { gram(l+1) [evict_last]; arrive(l+1); wait(l); softmax(l);
//            apply(l) [deltas demoted on last read] }
// ---------------------------------------------------------------------------
__global__ void __launch_bounds__(THREADS, OCC)
fused_kernel(const float* __restrict__ last,
             const float* __restrict__ deltas,
             const float* __restrict__ beta,
             float* __restrict__ out) {
    const int tid  = threadIdx.x;
    const int cta  = blockIdx.x;
    const int lane = tid & 31;
    const int wid  = tid >> 5;
    const unsigned long long pol = mk_sticky_policy();

    const int base = cta * THREADS + tid;   // same global map as R12

    __shared__ float sred[NWARP][NPAIR];
    __shared__ float Ws[KK * KK];

    // ------------------- gram phase for one layer -------------------------
    auto do_gram = [&](int l) {
        const float4* __restrict__ d4 =
            reinterpret_cast<const float4*>(deltas) + (size_t)l * KK * NVEC;

        float acc[NPAIR];
#pragma unroll
        for (int p = 0; p < NPAIR; ++p) acc[p] = 0.0f;

        for (int i = base; i < NVEC; i += 2 * GS) {
            const int i2 = i + GS;
            float4 v0[KK], v1[KK];
#pragma unroll
            for (int j = 0; j < KK; ++j)
                v0[j] = ld_sticky(&d4[(size_t)j * NVEC + i], pol);
            const bool has2 = (i2 < NVEC);
#pragma unroll
            for (int j = 0; j < KK; ++j)
                v1[j] = has2 ? ld_sticky(&d4[(size_t)j * NVEC + i2], pol)
                             : make_float4(0.f, 0.f, 0.f, 0.f);
            int p = 0;
#pragma unroll
            for (int a = 0; a < KK; ++a) {
#pragma unroll
                for (int b = a; b < KK; ++b) {
                    float s = fmaf(v0[a].x, v0[b].x, acc[p]);
                    s = fmaf(v0[a].y, v0[b].y, s);
                    s = fmaf(v0[a].z, v0[b].z, s);
                    s = fmaf(v0[a].w, v0[b].w, s);
                    s = fmaf(v1[a].x, v1[b].x, s);
                    s = fmaf(v1[a].y, v1[b].y, s);
                    s = fmaf(v1[a].z, v1[b].z, s);
                    s = fmaf(v1[a].w, v1[b].w, s);
                    acc[p] = s;
                    ++p;
                }
            }
        }

        // cross-warp reduce (sred reuse guarded by this syncthreads)
        __syncthreads();
#pragma unroll
        for (int p = 0; p < NPAIR; ++p) {
            float v = acc[p];
#pragma unroll
            for (int o = 16; o > 0; o >>= 1)
                v += __shfl_down_sync(0xffffffffu, v, o);
            if (lane == 0) sred[wid][p] = v;
        }
        __syncthreads();
        if (tid < NPAIR) {
            float s = 0.0f;
#pragma unroll
            for (int w = 0; w < NWARP; ++w) s += sred[w][tid];
            atomicAdd(&g_tri[l][tid * PAD], s);
        }
        // arrive: release our g_tri contribution, bump layer counter
        __threadfence();
        __syncthreads();
        if (tid == 0) atomicAdd(&g_bar[l], 1u);
    };

    // ------------------------------- schedule -----------------------------
    do_gram(0);

    for (int l = 0; l < LL; ++l) {
        if (l + 1 < LL) do_gram(l + 1);   // hides the wait below

        // wait for all gram(l) contributions
        if (tid == 0) {
            while (*(volatile unsigned*)&g_bar[l] < NCTA) __nanosleep(32);
        }
        __syncthreads();
        __threadfence();

        // softmax -> Ws in smem (every CTA redundantly; 8 threads)
        if (tid < KK) {
            const int k = tid;
            const float scale = rsqrtf((float)NN);
            float v[KK];
            float m = -1e30f;
#pragma unroll
            for (int j = 0; j < KK; ++j) {
                int a = k < j ? k : j;
                int b = k < j ? j : k;
                v[j] = g_tri[l][tri_idx(a, b) * PAD] * scale;
                m = fmaxf(m, v[j]);
            }
            float s = 0.0f;
#pragma unroll
            for (int j = 0; j < KK; ++j) {
                v[j] = __expf(v[j] - m);
                s += v[j];
            }
            float inv = 1.0f / s;
            float bcl = fminf(fmaxf(beta[l * KK + k], 0.0f), 1.0f);
#pragma unroll
            for (int j = 0; j < KK; ++j)
                Ws[k * KK + j] = bcl * v[j] * inv + ((j == k) ? 1.0f : 0.0f);
        }
        __syncthreads();

        // apply: out = last + Ws * deltas.  Last reader of deltas(l):
        // __ldcs demotes each consumed line, freeing sticky capacity.
        const float4* __restrict__ d4 =
            reinterpret_cast<const float4*>(deltas) + (size_t)l * KK * NVEC;
        const float4* __restrict__ p4 =
            reinterpret_cast<const float4*>(last) + (size_t)l * KK * NVEC;
        float4* __restrict__ o4 =
            reinterpret_cast<float4*>(out) + (size_t)l * KK * NVEC;

        for (int i = base; i < NVEC; i += GS) {
            float4 oacc[KK];
#pragma unroll
            for (int k = 0; k < KK; ++k)
                oacc[k] = __ldcs(&p4[(size_t)k * NVEC + i]);   // stream
#pragma unroll
            for (int j = 0; j < KK; ++j) {
                float4 v = __ldcs(&d4[(size_t)j * NVEC + i]);  // L2 hit + demote
#pragma unroll
                for (int k = 0; k < KK; ++k) {
                    float w = Ws[k * KK + j];
                    oacc[k].x = fmaf(w, v.x, oacc[k].x);
                    oacc[k].y = fmaf(w, v.y, oacc[k].y);
                    oacc[k].z = fmaf(w, v.z, oacc[k].z);
                    oacc[k].w = fmaf(w, v.w, oacc[k].w);
                }
            }
#pragma unroll
            for (int k = 0; k < KK; ++k)
                __stcs(&o4[(size_t)k * NVEC + i], oacc[k]);    // stream
        }
        __syncthreads();   // Ws/sred safe for next layer's reuse
    }
}

// ---------------------------------------------------------------------------
extern "C" void kernel_launch(void* const* d_in, const int* in_sizes, int n_in,
                              void* d_out, int out_size) {
    const float* last_params = (const float*)d_in[0];
    const float* deltas      = (const float*)d_in[1];
    const float* beta        = (const float*)d_in[2];
    float* out               = (float*)d_out;

    init_kernel<<<1, 1024>>>();
    fused_kernel<<<NCTA, THREADS>>>(last_params, deltas, beta, out);
}

// round 17
// speedup vs baseline: 1.1888x; 1.0583x over previous
#include <cuda_runtime.h>

// Problem constants
#define LL 8
#define KK 8
#define NN 1048576
#define NVEC (NN / 4)          // 262144 float4 per (l,k) row
#define NPAIR 36               // triangular 8x8
#define NSM 148
#define OCC 4
#define NCTA (NSM * OCC)       // 592 CTAs of 128 threads, all resident
#define THREADS 128
#define NWARP (THREADS / 32)   // 4
#define PAD 32                 // pad tri entries to separate 128B lines
#define GS (NCTA * THREADS)    // 75776 — identical stride to the R12 best

// Scratch (allocation-free rule: __device__ globals)
__device__ float    g_tri[LL][NPAIR * PAD];   // padded triangular Gram sums
__device__ unsigned g_bar[LL];                 // per-layer barrier counters

__device__ __forceinline__ int tri_idx(int a, int b) {
    return a * KK - (a * (a - 1)) / 2 + (b - a);
}

// L2 evict_last policy: lines loaded with this hint are sticky in L2.
__device__ __forceinline__ unsigned long long mk_sticky_policy() {
    unsigned long long p;
    asm("createpolicy.fractional.L2::evict_last.b64 %0, 1.0;" : "=l"(p));
    return p;
}
__device__ __forceinline__ float4 ld_sticky(const float4* a,
                                            unsigned long long pol) {
    float4 v;
    asm volatile("ld.global.L2::cache_hint.v4.f32 {%0,%1,%2,%3}, [%4], %5;"
                 : "=f"(v.x), "=f"(v.y), "=f"(v.z), "=f"(v.w)
                 : "l"(a), "l"(pol));
    return v;
}

// ---------------------------------------------------------------------------
// Init: reset barrier counters + zero tri accumulators (every replay)
// ---------------------------------------------------------------------------
__global__ void init_kernel() {
    const int t = threadIdx.x;
    if (t < LL) g_bar[t] = 0u;
    float* p = reinterpret_cast<float*>(g_tri);
    for (int i = t; i < LL * NPAIR * PAD; i += blockDim.x) p[i] = 0.0f;
}

// ---------------------------------------------------------------------------
// Persistent fused kernel == R12 best (identical memory pattern), but with
// 4 CTAs/SM x 128 threads: R16 showed 1 CTA/SM loses intra-SM phase overlap
// (SM idles while its only CTA spins at the barrier); 4 small CTAs keep the
// LSU fed through every wait window. Global thread->index map unchanged.
//   gram(0); arrive(0)
//   for l: { gram(l+1) [evict_last]; arrive(l+1); wait(l); softmax(l);
//            apply(l) [deltas demoted on last read] }
// ---------------------------------------------------------------------------
__global__ void __launch_bounds__(THREADS, OCC)
fused_kernel(const float* __restrict__ last,
             const float* __restrict__ deltas,
             const float* __restrict__ beta,
             float* __restrict__ out) {
    const int tid  = threadIdx.x;
    const int cta  = blockIdx.x;
    const int lane = tid & 31;
    const int wid  = tid >> 5;
    const unsigned long long pol = mk_sticky_policy();

    const int base = cta * THREADS + tid;   // same global map as R12

    __shared__ float sred[NWARP][NPAIR];
    __shared__ float Ws[KK * KK];

    // ------------------- gram phase for one layer -------------------------
    auto do_gram = [&](int l) {
        const float4* __restrict__ d4 =
            reinterpret_cast<const float4*>(deltas) + (size_t)l * KK * NVEC;

        float acc[NPAIR];
#pragma unroll
        for (int p = 0; p < NPAIR; ++p) acc[p] = 0.0f;

        for (int i = base; i < NVEC; i += 2 * GS) {
            const int i2 = i + GS;
            float4 v0[KK], v1[KK];
#pragma unroll
            for (int j = 0; j < KK; ++j)
                v0[j] = ld_sticky(&d4[(size_t)j * NVEC + i], pol);
            const bool has2 = (i2 < NVEC);
#pragma unroll
            for (int j = 0; j < KK; ++j)
                v1[j] = has2 ? ld_sticky(&d4[(size_t)j * NVEC + i2], pol)
                             : make_float4(0.f, 0.f, 0.f, 0.f);
            int p = 0;
#pragma unroll
            for (int a = 0; a < KK; ++a) {
#pragma unroll
                for (int b = a; b < KK; ++b) {
                    float s = fmaf(v0[a].x, v0[b].x, acc[p]);
                    s = fmaf(v0[a].y, v0[b].y, s);
                    s = fmaf(v0[a].z, v0[b].z, s);
                    s = fmaf(v0[a].w, v0[b].w, s);
                    s = fmaf(v1[a].x, v1[b].x, s);
                    s = fmaf(v1[a].y, v1[b].y, s);
                    s = fmaf(v1[a].z, v1[b].z, s);
                    s = fmaf(v1[a].w, v1[b].w, s);
                    acc[p] = s;
                    ++p;
                }
            }
        }

        // cross-warp reduce (sred reuse guarded by this syncthreads)
        __syncthreads();
#pragma unroll
        for (int p = 0; p < NPAIR; ++p) {
            float v = acc[p];
#pragma unroll
            for (int o = 16; o > 0; o >>= 1)
                v += __shfl_down_sync(0xffffffffu, v, o);
            if (lane == 0) sred[wid][p] = v;
        }
        __syncthreads();
        if (tid < NPAIR) {
            float s = 0.0f;
#pragma unroll
            for (int w = 0; w < NWARP; ++w) s += sred[w][tid];
            atomicAdd(&g_tri[l][tid * PAD], s);
        }
        // arrive: release our g_tri contribution, bump layer counter
        __threadfence();
        __syncthreads();
        if (tid == 0) atomicAdd(&g_bar[l], 1u);
    };

    // ------------------------------- schedule -----------------------------
    do_gram(0);

    for (int l = 0; l < LL; ++l) {
        if (l + 1 < LL) do_gram(l + 1);   // hides the wait below

        // wait for all gram(l) contributions
        if (tid == 0) {
            while (*(volatile unsigned*)&g_bar[l] < NCTA) __nanosleep(32);
        }
        __syncthreads();
        __threadfence();

        // softmax -> Ws in smem (every CTA redundantly; 8 threads)
        if (tid < KK) {
            const int k = tid;
            const float scale = rsqrtf((float)NN);
            float v[KK];
            float m = -1e30f;
#pragma unroll
            for (int j = 0; j < KK; ++j) {
                int a = k < j ? k : j;
                int b = k < j ? j : k;
                v[j] = g_tri[l][tri_idx(a, b) * PAD] * scale;
                m = fmaxf(m, v[j]);
            }
            float s = 0.0f;
#pragma unroll
            for (int j = 0; j < KK; ++j) {
                v[j] = __expf(v[j] - m);
                s += v[j];
            }
            float inv = 1.0f / s;
            float bcl = fminf(fmaxf(beta[l * KK + k], 0.0f), 1.0f);
#pragma unroll
            for (int j = 0; j < KK; ++j)
                Ws[k * KK + j] = bcl * v[j] * inv + ((j == k) ? 1.0f : 0.0f);
        }
        __syncthreads();

        // apply: out = last + Ws * deltas.  Last reader of deltas(l):
        // __ldcs demotes each consumed line, freeing sticky capacity.
        const float4* __restrict__ d4 =
            reinterpret_cast<const float4*>(deltas) + (size_t)l * KK * NVEC;
        const float4* __restrict__ p4 =
            reinterpret_cast<const float4*>(last) + (size_t)l * KK * NVEC;
        float4* __restrict__ o4 =
            reinterpret_cast<float4*>(out) + (size_t)l * KK * NVEC;

        for (int i = base; i < NVEC; i += GS) {
            float4 oacc[KK];
#pragma unroll
            for (int k = 0; k < KK; ++k)
                oacc[k] = __ldcs(&p4[(size_t)k * NVEC + i]);   // stream
#pragma unroll
            for (int j = 0; j < KK; ++j) {
                float4 v = __ldcs(&d4[(size_t)j * NVEC + i]);  // L2 hit + demote
#pragma unroll
                for (int k = 0; k < KK; ++k) {
                    float w = Ws[k * KK + j];
                    oacc[k].x = fmaf(w, v.x, oacc[k].x);
                    oacc[k].y = fmaf(w, v.y, oacc[k].y);
                    oacc[k].z = fmaf(w, v.z, oacc[k].z);
                    oacc[k].w = fmaf(w, v.w, oacc[k].w);
                }
            }
#pragma unroll
            for (int k = 0; k < KK; ++k)
                __stcs(&o4[(size_t)k * NVEC + i], oacc[k]);    // stream
        }
        __syncthreads();   // Ws/sred safe for next layer's reuse
    }
}

// ---------------------------------------------------------------------------
extern "C" void kernel_launch(void* const* d_in, const int* in_sizes, int n_in,
                              void* d_out, int out_size) {
    const float* last_params = (const float*)d_in[0];
    const float* deltas      = (const float*)d_in[1];
    const float* beta        = (const float*)d_in[2];
    float* out               = (float*)d_out;

    init_kernel<<<1, 1024>>>();
    fused_kernel<<<NCTA, THREADS>>>(last_params, deltas, beta, out);
}